// round 7
// baseline (speedup 1.0000x reference)
#include <cuda_runtime.h>

#define NUM_ENT   14541
#define EMBED_D   200
#define D4        50           // D/4 (4 int8 elems per u32 word)
#define BATCH     256
#define TILE_B    64
#define TILE_N    131          // 111 * 131 == 14541 exactly
#define N_TILES   111
#define B_TILES   4
#define THREADS   256
#define ENT_WPR   53           // ent smem row pitch in words (gcd(53,32)=1 -> conflict-free)
#define ENT_W     6944         // 131*53 = 6943, padded to 16B multiple for LDS.128 after it
#define OBJ_W     (D4 * 64)    // [d4][wg][i] packed words
#define SMEM_W    (ENT_W + OBJ_W)   // 10144 words = 40576 B

typedef unsigned int u32;

// int8-quantized tables (scale 16): ent rows packed 50 words each
__device__ u32 g_entq[NUM_ENT * D4];
__device__ u32 g_objq[BATCH * D4];

__device__ __forceinline__ u32 quant4(float4 v) {
    int q0 = __float2int_rn(fminf(fmaxf(v.x * 16.f, -127.f), 127.f));
    int q1 = __float2int_rn(fminf(fmaxf(v.y * 16.f, -127.f), 127.f));
    int q2 = __float2int_rn(fminf(fmaxf(v.z * 16.f, -127.f), 127.f));
    int q3 = __float2int_rn(fminf(fmaxf(v.w * 16.f, -127.f), 127.f));
    return (q0 & 255) | ((q1 & 255) << 8) | ((q2 & 255) << 16) | ((q3 & 255) << 24);
}

__global__ void quant_ent_kernel(const float* __restrict__ ent) {
    int idx = blockIdx.x * blockDim.x + threadIdx.x;
    if (idx < NUM_ENT * D4) {
        float4 v = *reinterpret_cast<const float4*>(ent + 4 * idx);
        g_entq[idx] = quant4(v);
    }
}

__global__ void quant_obj_kernel(const float* __restrict__ ent,
                                 const float* __restrict__ rel_e,
                                 const int* __restrict__ sub,
                                 const int* __restrict__ rel) {
    int idx = blockIdx.x * blockDim.x + threadIdx.x;
    if (idx < BATCH * D4) {
        int b = idx / D4, d4 = idx - b * D4;
        float4 a = *reinterpret_cast<const float4*>(ent + sub[b] * EMBED_D + 4 * d4);
        float4 r = *reinterpret_cast<const float4*>(rel_e + rel[b] * EMBED_D + 4 * d4);
        float4 s = make_float4(a.x + r.x, a.y + r.y, a.z + r.z, a.w + r.w);
        g_objq[idx] = quant4(s);
    }
}

// fused SIMD abs-diff + accumulate: acc += sum_bytes(|a_k - b_k|)
#define SAD(accv, a, b)                                          \
    asm("vabsdiff4.s32.s32.s32.add %0, %1, %2, %0;"              \
        : "+r"(accv) : "r"(a), "r"(b))

__global__ void __launch_bounds__(THREADS, 3)
transe_kernel(float* __restrict__ out) {
    __shared__ u32 sm[SMEM_W];

    const int tid = threadIdx.x;
    const int n0  = blockIdx.x * TILE_N;
    const int b0  = blockIdx.y * TILE_B;

    // ---- ent tile: global rows packed [n][50] -> smem [n][pitch 53] ----
    {
        const u32* src = g_entq + n0 * D4;   // contiguous 131*50 words
        for (int w = tid; w < TILE_N * D4; w += THREADS) {
            int n = w / D4, d4 = w - n * D4;
            sm[n * ENT_WPR + d4] = src[w];
        }
    }
    // ---- obj tile: [d4][wg][i] with b = wg + 8*i ----
    for (int w = tid; w < TILE_B * D4; w += THREADS) {
        int b = w / D4, d4 = w - b * D4;
        sm[ENT_W + d4 * 64 + (b & 7) * 8 + (b >> 3)] = g_objq[(b0 + b) * D4 + d4];
    }
    __syncthreads();

    const int tn = tid & 31;
    const int wg = tid >> 5;   // 8 warps

    u32 acc[32];
#pragma unroll
    for (int k = 0; k < 32; k++) acc[k] = 0u;

    const u32* ep = sm + tn * ENT_WPR;            // e_j at ep[j*32*ENT_WPR + d4]
    const u32* ob = sm + ENT_W + wg * 8;          // 8 words, 32B-aligned

#pragma unroll 5
    for (int d4 = 0; d4 < D4; d4++) {
        uint4 oa = *reinterpret_cast<const uint4*>(ob);        // LDS.128 broadcast
        uint4 obx = *reinterpret_cast<const uint4*>(ob + 4);
        u32 o[8] = {oa.x, oa.y, oa.z, oa.w, obx.x, obx.y, obx.z, obx.w};
        u32 e[4];
#pragma unroll
        for (int j = 0; j < 4; j++) e[j] = ep[j * 32 * ENT_WPR];  // conflict-free
#pragma unroll
        for (int i = 0; i < 8; i++)
#pragma unroll
            for (int j = 0; j < 4; j++)
                SAD(acc[i * 4 + j], o[i], e[j]);
        ep += 1;
        ob += 64;
    }

    // ---- main 128 columns ----
#pragma unroll
    for (int k = 0; k < 32; k++) {
        int i = k >> 2, j = k & 3;
        int b = b0 + wg + 8 * i;
        float dist = (float)acc[k] * 0.0625f;           // /16
        out[b * NUM_ENT + (n0 + tn + 32 * j)] =
            __fdividef(1.0f, 1.0f + __expf(dist - 9.0f));
    }

    // ---- strip: columns 128..130 (3 per tile), threads 0..191 ----
    if (tid < TILE_B * 3) {
        int sb = tid / 3;
        int sn = 128 + (tid - sb * 3);
        const u32* es = sm + sn * ENT_WPR;
        const u32* os = sm + ENT_W + (sb & 7) * 8 + (sb >> 3);
        u32 sacc = 0u;
#pragma unroll 5
        for (int d4 = 0; d4 < D4; d4++) {
            u32 ev = es[d4];
            u32 ov = os[d4 * 64];
            SAD(sacc, ov, ev);
        }
        float dist = (float)sacc * 0.0625f;
        out[(b0 + sb) * NUM_ENT + (n0 + sn)] =
            __fdividef(1.0f, 1.0f + __expf(dist - 9.0f));
    }
}

extern "C" void kernel_launch(void* const* d_in, const int* in_sizes, int n_in,
                              void* d_out, int out_size) {
    const float* ent   = (const float*)d_in[0];
    const float* rel_e = (const float*)d_in[1];
    const int*   sub   = (const int*)d_in[2];
    const int*   rel   = (const int*)d_in[3];
    float* out = (float*)d_out;

    quant_ent_kernel<<<(NUM_ENT * D4 + THREADS - 1) / THREADS, THREADS>>>(ent);
    quant_obj_kernel<<<(BATCH * D4 + THREADS - 1) / THREADS, THREADS>>>(ent, rel_e, sub, rel);
    transe_kernel<<<dim3(N_TILES, B_TILES), THREADS>>>(out);
}

// round 9
// speedup vs baseline: 4.5908x; 4.5908x over previous
#include <cuda_runtime.h>
#include <cuda_fp16.h>

#define NUM_ENT   14541
#define EMBED_D   200
#define D2        100
#define BATCH     256
#define TILE_B    64
#define TILE_N    131          // 111 * 131 == 14541 exactly
#define N_TILES   111
#define B_TILES   4
#define THREADS   256
#define ENT_W     (D2 * TILE_N)   // 13100 u32 (half2 each)
#define SGN_W     (D2 * 64)       // 6400 u32
#define SMEM_BYTES ((ENT_W + SGN_W) * 4)   // 78000
#define THRESH    140.0f

typedef unsigned int u32;

__device__ float g_obj[BATCH * EMBED_D];   // exact fp32 obj (fallback path)
__device__ u32   g_sgn[BATCH * D2];        // sign(obj) as packed half2 (+-1)
__device__ float g_S[BATCH];               // sum |obj_d|

// ---- prep: obj = ent[sub] + rel_e[rel]; signs; S = sum|obj| ----
__global__ void prep_obj(const float* __restrict__ ent,
                         const float* __restrict__ rel_e,
                         const int* __restrict__ sub,
                         const int* __restrict__ rel) {
    int b = blockIdx.x, t = threadIdx.x;   // 128 threads
    __shared__ float red[128];
    float s = 0.f;
    if (t < D2) {
        const float* ep = ent + sub[b] * EMBED_D + 2 * t;
        const float* rp = rel_e + rel[b] * EMBED_D + 2 * t;
        float o0 = ep[0] + rp[0], o1 = ep[1] + rp[1];
        g_obj[b * EMBED_D + 2 * t]     = o0;
        g_obj[b * EMBED_D + 2 * t + 1] = o1;
        __half2 sg = __floats2half2_rn(o0 >= 0.f ? 1.f : -1.f,
                                       o1 >= 0.f ? 1.f : -1.f);
        g_sgn[b * D2 + t] = *reinterpret_cast<u32*>(&sg);
        s = fabsf(o0) + fabsf(o1);
    }
    red[t] = s;
    __syncthreads();
    for (int off = 64; off; off >>= 1) {
        if (t < off) red[t] += red[t + off];
        __syncthreads();
    }
    if (t == 0) g_S[b] = red[0];
}

// jax-matching sigmoid (two-branch; preserves subnormal behavior)
__device__ __forceinline__ float sigmoid_score(float dist) {
    float x = 9.f - dist;
    if (x >= 0.f) return 1.f / (1.f + expf(-x));
    float ex = expf(x);
    return ex / (1.f + ex);
}

// exact fp32 score for pairs the bound can't certify (rare)
__device__ __noinline__ float exact_pair(const float* __restrict__ ent, int b, int n) {
    const float* o = g_obj + b * EMBED_D;
    const float* e = ent + n * EMBED_D;
    float d = 0.f;
#pragma unroll 4
    for (int q = 0; q < EMBED_D; q++) d += fabsf(o[q] - e[q]);
    return sigmoid_score(d);
}

__global__ void __launch_bounds__(THREADS, 2)
transe_kernel(const float* __restrict__ ent, float* __restrict__ out) {
    extern __shared__ u32 sm[];
    u32* e_s = sm;              // [d2][131]  half2(e_d, e_{d+1})
    u32* s_s = sm + ENT_W;      // [d2][wg(8)][i(8)] sign half2

    const int tid = threadIdx.x;
    const int n0  = blockIdx.x * TILE_N;
    const int b0  = blockIdx.y * TILE_B;

    // ent tile: fp32 -> half2, transposed [d2][n]
    for (int idx = tid; idx < TILE_N * D2; idx += THREADS) {
        int n = idx / D2, d2 = idx - n * D2;
        float2 v = *reinterpret_cast<const float2*>(ent + (n0 + n) * EMBED_D + 2 * d2);
        __half2 h = __floats2half2_rn(v.x, v.y);
        e_s[d2 * TILE_N + n] = *reinterpret_cast<u32*>(&h);
    }
    // sign tile: [d2][wg][i], b = wg + 8*i
    for (int idx = tid; idx < TILE_B * D2; idx += THREADS) {
        int b = idx / D2, d2 = idx - b * D2;
        s_s[d2 * 64 + (b & 7) * 8 + (b >> 3)] = g_sgn[(b0 + b) * D2 + d2];
    }
    __syncthreads();

    const int tn = tid & 31;
    const int wg = tid >> 5;   // 8 warps

    __half2 acc[32];
#pragma unroll
    for (int k = 0; k < 32; k++) acc[k] = __floats2half2_rn(0.f, 0.f);

    const u32* ep = e_s + tn;
    const uint4* gp = reinterpret_cast<const uint4*>(s_s + wg * 8);  // 32B-aligned

#pragma unroll 4
    for (int d2 = 0; d2 < D2; d2++) {
        uint4 ga = gp[0], gb = gp[1];                 // 2x LDS.128 broadcast
        u32 gw[8] = {ga.x, ga.y, ga.z, ga.w, gb.x, gb.y, gb.z, gb.w};
        u32 ew[4];
#pragma unroll
        for (int j = 0; j < 4; j++) ew[j] = ep[32 * j];   // conflict-free
#pragma unroll
        for (int i = 0; i < 8; i++) {
            __half2 sg = *reinterpret_cast<__half2*>(&gw[i]);
#pragma unroll
            for (int j = 0; j < 4; j++) {
                __half2 ev = *reinterpret_cast<__half2*>(&ew[j]);
                acc[i * 4 + j] = __hfma2(sg, ev, acc[i * 4 + j]);  // 1 instr / 2 elems
            }
        }
        ep += TILE_N;
        gp += 16;   // 64 u32
    }

    // epilogue: lb = S - dot; certified-zero or exact fallback
#pragma unroll
    for (int i = 0; i < 8; i++) {
        int b = b0 + wg + 8 * i;
        float S = g_S[b];
#pragma unroll
        for (int j = 0; j < 4; j++) {
            __half2 a = acc[i * 4 + j];
            float lb = S - (__low2float(a) + __high2float(a));
            int n = n0 + tn + 32 * j;
            float v = 0.f;
            if (lb <= THRESH) v = exact_pair(ent, b, n);
            out[b * NUM_ENT + n] = v;
        }
    }

    // strip: columns 128..130, threads 0..191
    if (tid < TILE_B * 3) {
        int sb = tid / 3;
        int sn = 128 + (tid - sb * 3);
        __half2 sa = __floats2half2_rn(0.f, 0.f);
        const u32* gs = s_s + (sb & 7) * 8 + (sb >> 3);
        const u32* es = e_s + sn;
#pragma unroll 4
        for (int d2 = 0; d2 < D2; d2++) {
            u32 gwv = gs[d2 * 64], ewv = es[d2 * TILE_N];
            sa = __hfma2(*reinterpret_cast<__half2*>(&gwv),
                         *reinterpret_cast<__half2*>(&ewv), sa);
        }
        float lb = g_S[b0 + sb] - (__low2float(sa) + __high2float(sa));
        float v = 0.f;
        if (lb <= THRESH) v = exact_pair(ent, b0 + sb, n0 + sn);
        out[(b0 + sb) * NUM_ENT + (n0 + sn)] = v;
    }
}

extern "C" void kernel_launch(void* const* d_in, const int* in_sizes, int n_in,
                              void* d_out, int out_size) {
    const float* ent   = (const float*)d_in[0];
    const float* rel_e = (const float*)d_in[1];
    const int*   sub   = (const int*)d_in[2];
    const int*   rel   = (const int*)d_in[3];
    float* out = (float*)d_out;

    cudaFuncSetAttribute(transe_kernel,
                         cudaFuncAttributeMaxDynamicSharedMemorySize, SMEM_BYTES);

    prep_obj<<<BATCH, 128>>>(ent, rel_e, sub, rel);
    transe_kernel<<<dim3(N_TILES, B_TILES), THREADS, SMEM_BYTES>>>(ent, out);
}

// round 15
// speedup vs baseline: 5.8474x; 1.2737x over previous
#include <cuda_runtime.h>
#include <cuda_bf16.h>

#define NUM_ENT   14541
#define EMBED_D   200
#define D2        100
#define BATCH     256
#define KPAD      208            // 13 k-steps of 16
#define KW        104            // words per row (bf16x2)
#define KSTEPS    13
#define M_TILE    128
#define M_TILES   114            // 114*128 = 14592 >= 14541
#define ENT_ROWS  14592
#define THREADS   256
#define PITCH_W   108            // smem row pitch in words: bank-stride 12, conflict-free
#define A_BYTES   (128 * PITCH_W * 4)          // 55296
#define B_BYTES   (256 * PITCH_W * 4)          // 110592
#define S_OFF     (A_BYTES + B_BYTES)          // 165888
#define SMEM_TOT  (S_OFF + BATCH * 4)          // 166912
#define THRESH    125.0f

typedef unsigned int u32;

__device__ u32   g_entb[ENT_ROWS * KW];   // bf16x2, zero-padded rows/cols
__device__ u32   g_sgnb[BATCH * KW];      // bf16x2 of sign(obj), 0-padded K
__device__ float g_obj[BATCH * EMBED_D];  // exact fp32 obj (fallback path)
__device__ float g_S[BATCH];              // sum |obj|

// ---------------- prep ----------------
__global__ void prep_ent(const float* __restrict__ ent) {
    int idx = blockIdx.x * blockDim.x + threadIdx.x;
    if (idx >= ENT_ROWS * KW) return;
    int row = idx / KW, w = idx - row * KW;
    float a = 0.f, b = 0.f;
    if (row < NUM_ENT && 2 * w < EMBED_D) {
        a = ent[row * EMBED_D + 2 * w];
        b = ent[row * EMBED_D + 2 * w + 1];
    }
    __nv_bfloat162 h = __floats2bfloat162_rn(a, b);
    g_entb[idx] = *reinterpret_cast<u32*>(&h);
}

__global__ void prep_obj(const float* __restrict__ ent,
                         const float* __restrict__ rel_e,
                         const int* __restrict__ sub,
                         const int* __restrict__ rel) {
    int b = blockIdx.x, t = threadIdx.x;   // 128 threads
    __shared__ float red[128];
    float s = 0.f;
    if (t < D2) {
        const float* ep = ent + sub[b] * EMBED_D + 2 * t;
        const float* rp = rel_e + rel[b] * EMBED_D + 2 * t;
        float o0 = ep[0] + rp[0], o1 = ep[1] + rp[1];
        g_obj[b * EMBED_D + 2 * t]     = o0;
        g_obj[b * EMBED_D + 2 * t + 1] = o1;
        __nv_bfloat162 sg = __floats2bfloat162_rn(o0 >= 0.f ? 1.f : -1.f,
                                                  o1 >= 0.f ? 1.f : -1.f);
        g_sgnb[b * KW + t] = *reinterpret_cast<u32*>(&sg);
        s = fabsf(o0) + fabsf(o1);
    } else if (t < KW) {
        g_sgnb[b * KW + t] = 0u;           // K padding
    }
    red[t] = s;
    __syncthreads();
    for (int off = 64; off; off >>= 1) {
        if (t < off) red[t] += red[t + off];
        __syncthreads();
    }
    if (t == 0) g_S[b] = red[0];
}

// ---------------- exact fallback (validated in R9) ----------------
__device__ __forceinline__ float sigmoid_score(float dist) {
    float x = 9.f - dist;
    if (x >= 0.f) return 1.f / (1.f + expf(-x));
    float ex = expf(x);
    return ex / (1.f + ex);
}
__device__ __noinline__ float exact_pair(const float* __restrict__ ent, int b, int n) {
    const float* o = g_obj + b * EMBED_D;
    const float* e = ent + n * EMBED_D;
    float d = 0.f;
#pragma unroll 4
    for (int q = 0; q < EMBED_D; q++) d += fabsf(o[q] - e[q]);
    return sigmoid_score(d);
}

__device__ __forceinline__ void mma16816(float c[4], u32 a0, u32 a1, u32 a2, u32 a3,
                                         u32 b0, u32 b1) {
    asm("mma.sync.aligned.m16n8k16.row.col.f32.bf16.bf16.f32 "
        "{%0,%1,%2,%3}, {%4,%5,%6,%7}, {%8,%9}, {%0,%1,%2,%3};"
        : "+f"(c[0]), "+f"(c[1]), "+f"(c[2]), "+f"(c[3])
        : "r"(a0), "r"(a1), "r"(a2), "r"(a3), "r"(b0), "r"(b1));
}

// ---------------- main kernel ----------------
__global__ void __launch_bounds__(THREADS, 1)
transe_mma_kernel(const float* __restrict__ ent, float* __restrict__ out) {
    extern __shared__ char smem[];
    u32*   A_s = reinterpret_cast<u32*>(smem);             // [128][PITCH_W]
    u32*   B_s = reinterpret_cast<u32*>(smem + A_BYTES);   // [256][PITCH_W]
    float* S_s = reinterpret_cast<float*>(smem + S_OFF);   // [256]

    const int tid = threadIdx.x;
    const int m0  = blockIdx.x * M_TILE;

    // ---- A tile: ent rows m0..m0+127, 26 uint4 per row ----
    {
        const uint4* src = reinterpret_cast<const uint4*>(g_entb) + (size_t)m0 * 26;
        for (int c = tid; c < 128 * 26; c += THREADS) {
            int r = c / 26, q = c - r * 26;
            *reinterpret_cast<uint4*>(&A_s[r * PITCH_W + q * 4]) = src[c];
        }
    }
    // ---- B tile: sgn rows 0..255 ----
    {
        const uint4* src = reinterpret_cast<const uint4*>(g_sgnb);
        for (int c = tid; c < 256 * 26; c += THREADS) {
            int r = c / 26, q = c - r * 26;
            *reinterpret_cast<uint4*>(&B_s[r * PITCH_W + q * 4]) = src[c];
        }
    }
    if (tid < BATCH) S_s[tid] = g_S[tid];
    __syncthreads();

    const int lane = tid & 31, w = tid >> 5;
    const int g = lane >> 2, t4 = lane & 3;
    const int ra0 = (w * 16 + g) * PITCH_W;
    const int ra1 = ra0 + 8 * PITCH_W;
    const int mr0 = m0 + w * 16 + g;       // output rows mr0, mr0+8

#pragma unroll 1
    for (int h = 0; h < 2; h++) {
        float acc[16][4];
#pragma unroll
        for (int j = 0; j < 16; j++)
#pragma unroll
            for (int q = 0; q < 4; q++) acc[j][q] = 0.f;

#pragma unroll 1
        for (int k = 0; k < KSTEPS; k++) {
            const int kb = k * 8 + t4;
            u32 a0 = A_s[ra0 + kb],     a1 = A_s[ra1 + kb];
            u32 a2 = A_s[ra0 + kb + 4], a3 = A_s[ra1 + kb + 4];
            const int rb0 = (h * 128 + g) * PITCH_W + kb;
#pragma unroll
            for (int j = 0; j < 16; j++) {
                u32 b0 = B_s[rb0 + j * 8 * PITCH_W];
                u32 b1 = B_s[rb0 + j * 8 * PITCH_W + 4];
                mma16816(acc[j], a0, a1, a2, a3, b0, b1);
            }
        }

        // ---- epilogue: lb = S - dot; certified zero or exact fallback ----
        const bool v0 = (mr0 < NUM_ENT);
        const bool v1 = (mr0 + 8 < NUM_ENT);
#pragma unroll
        for (int j = 0; j < 16; j++) {
            int bc0 = h * 128 + j * 8 + 2 * t4;
            int bc1 = bc0 + 1;
            float S0 = S_s[bc0], S1 = S_s[bc1];
            if (v0) {
                float lb = S0 - acc[j][0];
                out[(size_t)bc0 * NUM_ENT + mr0] =
                    (lb <= THRESH) ? exact_pair(ent, bc0, mr0) : 0.f;
                lb = S1 - acc[j][1];
                out[(size_t)bc1 * NUM_ENT + mr0] =
                    (lb <= THRESH) ? exact_pair(ent, bc1, mr0) : 0.f;
            }
            if (v1) {
                float lb = S0 - acc[j][2];
                out[(size_t)bc0 * NUM_ENT + mr0 + 8] =
                    (lb <= THRESH) ? exact_pair(ent, bc0, mr0 + 8) : 0.f;
                lb = S1 - acc[j][3];
                out[(size_t)bc1 * NUM_ENT + mr0 + 8] =
                    (lb <= THRESH) ? exact_pair(ent, bc1, mr0 + 8) : 0.f;
            }
        }
    }
}

extern "C" void kernel_launch(void* const* d_in, const int* in_sizes, int n_in,
                              void* d_out, int out_size) {
    const float* ent   = (const float*)d_in[0];
    const float* rel_e = (const float*)d_in[1];
    const int*   sub   = (const int*)d_in[2];
    const int*   rel   = (const int*)d_in[3];
    float* out = (float*)d_out;

    cudaFuncSetAttribute(transe_mma_kernel,
                         cudaFuncAttributeMaxDynamicSharedMemorySize, SMEM_TOT);

    prep_ent<<<(ENT_ROWS * KW + 255) / 256, 256>>>(ent);
    prep_obj<<<BATCH, 128>>>(ent, rel_e, sub, rel);
    transe_mma_kernel<<<M_TILES, THREADS, SMEM_TOT>>>(ent, out);
}

// round 17
// speedup vs baseline: 7.4042x; 1.2662x over previous
#include <cuda_runtime.h>
#include <cuda_bf16.h>

#define NUM_ENT   14541
#define EMBED_D   200
#define D2        100
#define BATCH     256
#define KW        104            // bf16x2 words per row (K=208 padded)
#define KSTEPS    13
#define N_TILE    128            // entities per CTA
#define N_TILES   114            // 114*128 = 14592 >= 14541
#define THREADS   512
#define PITCH_W   108            // smem row pitch (words): bank-stride 12, conflict-free
#define A_OFF     0                              // sgn tile [256][108]
#define B_OFF     (256 * PITCH_W * 4)            // ent tile [128][108] -> 110592
#define S_OFF     (B_OFF + 128 * PITCH_W * 4)    // 165888
#define SMEM_TOT  (S_OFF + BATCH * 4)            // 166912
#define STAGE_P   132            // stage pitch (floats); 256*132*4 = 135168 fits
#define THRESH    125.0f

typedef unsigned int u32;

__device__ u32   g_sgnb[BATCH * KW];      // bf16x2 of sign(obj), 0-padded K
__device__ float g_obj[BATCH * EMBED_D];  // exact fp32 obj (fallback path)
__device__ float g_S[BATCH];              // sum |obj|

// ---------------- prep: obj, sign, S ----------------
__global__ void prep_obj(const float* __restrict__ ent,
                         const float* __restrict__ rel_e,
                         const int* __restrict__ sub,
                         const int* __restrict__ rel) {
    int b = blockIdx.x, t = threadIdx.x;   // 128 threads
    __shared__ float red[128];
    float s = 0.f;
    if (t < D2) {
        const float* ep = ent + sub[b] * EMBED_D + 2 * t;
        const float* rp = rel_e + rel[b] * EMBED_D + 2 * t;
        float o0 = ep[0] + rp[0], o1 = ep[1] + rp[1];
        g_obj[b * EMBED_D + 2 * t]     = o0;
        g_obj[b * EMBED_D + 2 * t + 1] = o1;
        __nv_bfloat162 sg = __floats2bfloat162_rn(o0 >= 0.f ? 1.f : -1.f,
                                                  o1 >= 0.f ? 1.f : -1.f);
        g_sgnb[b * KW + t] = *reinterpret_cast<u32*>(&sg);
        s = fabsf(o0) + fabsf(o1);
    } else if (t < KW) {
        g_sgnb[b * KW + t] = 0u;           // K padding
    }
    red[t] = s;
    __syncthreads();
    for (int off = 64; off; off >>= 1) {
        if (t < off) red[t] += red[t + off];
        __syncthreads();
    }
    if (t == 0) g_S[b] = red[0];
}

// ---------------- exact fallback (validated) ----------------
__device__ __forceinline__ float sigmoid_score(float dist) {
    float x = 9.f - dist;
    if (x >= 0.f) return 1.f / (1.f + expf(-x));
    float ex = expf(x);
    return ex / (1.f + ex);
}
__device__ __noinline__ float exact_pair(const float* __restrict__ ent, int b, int n) {
    const float* o = g_obj + b * EMBED_D;
    const float* e = ent + n * EMBED_D;
    float d = 0.f;
#pragma unroll 4
    for (int q = 0; q < EMBED_D; q++) d += fabsf(o[q] - e[q]);
    return sigmoid_score(d);
}

__device__ __forceinline__ void mma16816(float c[4], u32 a0, u32 a1, u32 a2, u32 a3,
                                         u32 b0, u32 b1) {
    asm("mma.sync.aligned.m16n8k16.row.col.f32.bf16.bf16.f32 "
        "{%0,%1,%2,%3}, {%4,%5,%6,%7}, {%8,%9}, {%0,%1,%2,%3};"
        : "+f"(c[0]), "+f"(c[1]), "+f"(c[2]), "+f"(c[3])
        : "r"(a0), "r"(a1), "r"(a2), "r"(a3), "r"(b0), "r"(b1));
}
#define LDM_X4(r0, r1, r2, r3, addr)                                   \
    asm volatile("ldmatrix.sync.aligned.m8n8.x4.shared.b16 "           \
                 "{%0,%1,%2,%3}, [%4];"                                \
                 : "=r"(r0), "=r"(r1), "=r"(r2), "=r"(r3) : "r"(addr))

// ---------------- main kernel ----------------
__global__ void __launch_bounds__(THREADS, 1)
transe_mma_kernel(const float* __restrict__ ent, float* __restrict__ out) {
    extern __shared__ char smem[];
    u32*   A_s   = reinterpret_cast<u32*>(smem + A_OFF);   // sgn [256][108]
    u32*   B_s   = reinterpret_cast<u32*>(smem + B_OFF);   // ent [128][108]
    float* S_s   = reinterpret_cast<float*>(smem + S_OFF);
    float* stage = reinterpret_cast<float*>(smem);         // [256][132] (reuse)

    const int tid = threadIdx.x;
    const int n0  = blockIdx.x * N_TILE;

    // ---- sgn tile: straight copy, 256 rows x 26 uint4 ----
    {
        const uint4* src = reinterpret_cast<const uint4*>(g_sgnb);
        for (int c = tid; c < 256 * 26; c += THREADS) {
            int r = c / 26, q = c - r * 26;
            *reinterpret_cast<uint4*>(&A_s[r * PITCH_W + q * 4]) = src[c];
        }
    }
    // ---- ent tile: fused fp32 -> bf16 convert (kills prep_ent kernel) ----
    for (int c = tid; c < 128 * 26; c += THREADS) {
        int r = c / 26, q = c - r * 26;
        int rg = n0 + r;
        uint4 w = make_uint4(0u, 0u, 0u, 0u);
        if (q < 25 && rg < NUM_ENT) {
            const float4* fp = reinterpret_cast<const float4*>(ent + (size_t)rg * EMBED_D + 8 * q);
            float4 f0 = fp[0], f1 = fp[1];
            __nv_bfloat162 h0 = __floats2bfloat162_rn(f0.x, f0.y);
            __nv_bfloat162 h1 = __floats2bfloat162_rn(f0.z, f0.w);
            __nv_bfloat162 h2 = __floats2bfloat162_rn(f1.x, f1.y);
            __nv_bfloat162 h3 = __floats2bfloat162_rn(f1.z, f1.w);
            w.x = *reinterpret_cast<u32*>(&h0);
            w.y = *reinterpret_cast<u32*>(&h1);
            w.z = *reinterpret_cast<u32*>(&h2);
            w.w = *reinterpret_cast<u32*>(&h3);
        }
        *reinterpret_cast<uint4*>(&B_s[r * PITCH_W + q * 4]) = w;
    }
    if (tid < BATCH) S_s[tid] = g_S[tid];
    __syncthreads();

    const int lane = tid & 31, w = tid >> 5;   // 16 warps, warp = m16 batch tile
    u32 sbase;
    asm("{ .reg .u64 t; cvta.to.shared.u64 t, %1; cvt.u32.u64 %0, t; }"
        : "=r"(sbase) : "l"(smem));

    // ldmatrix lane addresses
    u32 a_addr = sbase + A_OFF +
        (u32)(((w * 16 + (lane & 7) + ((lane >> 3) & 1) * 8) * PITCH_W +
               ((lane >> 4) & 1) * 4) * 4);
    u32 b_addr[8];
#pragma unroll
    for (int p = 0; p < 8; p++)
        b_addr[p] = sbase + B_OFF +
            (u32)(((p * 16 + ((lane >> 4) & 1) * 8 + (lane & 7)) * PITCH_W +
                   ((lane >> 3) & 1) * 4) * 4);

    float acc[16][4];
#pragma unroll
    for (int j = 0; j < 16; j++)
#pragma unroll
        for (int q = 0; q < 4; q++) acc[j][q] = 0.f;

#pragma unroll 1
    for (int k = 0; k < KSTEPS; k++) {
        u32 a0, a1, a2, a3;
        LDM_X4(a0, a1, a2, a3, a_addr);
        a_addr += 32;
#pragma unroll
        for (int p = 0; p < 8; p++) {
            u32 b0, b1, b2, b3;
            LDM_X4(b0, b1, b2, b3, b_addr[p]);
            b_addr[p] += 32;
            mma16816(acc[2 * p],     a0, a1, a2, a3, b0, b1);
            mma16816(acc[2 * p + 1], a0, a1, a2, a3, b2, b3);
        }
    }

    // ---- compute scores in-place (before smem reuse) ----
    const int br = w * 16 + (lane >> 2);     // batch rows br, br+8
    const int t4 = lane & 3;
    const float S0 = S_s[br], S1 = S_s[br + 8];
#pragma unroll
    for (int j = 0; j < 16; j++) {
        int n = n0 + j * 8 + 2 * t4;
#pragma unroll
        for (int q = 0; q < 4; q++) {
            int nn = n + (q & 1);
            float lb = ((q < 2) ? S0 : S1) - acc[j][q];
            float v = 0.f;
            if (lb <= THRESH && nn < NUM_ENT)
                v = exact_pair(ent, (q < 2) ? br : br + 8, nn);
            acc[j][q] = v;
        }
    }
    __syncthreads();   // all warps done reading A_s/B_s

    // ---- stage results [256][STAGE_P] then coalesced copy out ----
#pragma unroll
    for (int j = 0; j < 16; j++) {
        int nl = j * 8 + 2 * t4;
        *reinterpret_cast<float2*>(&stage[br * STAGE_P + nl]) =
            make_float2(acc[j][0], acc[j][1]);
        *reinterpret_cast<float2*>(&stage[(br + 8) * STAGE_P + nl]) =
            make_float2(acc[j][2], acc[j][3]);
    }
    __syncthreads();

#pragma unroll 4
    for (int idx = tid; idx < 256 * 128; idx += THREADS) {
        int r = idx >> 7, ncol = idx & 127;
        int n = n0 + ncol;
        if (n < NUM_ENT)
            out[(size_t)r * NUM_ENT + n] = stage[r * STAGE_P + ncol];
    }
}

extern "C" void kernel_launch(void* const* d_in, const int* in_sizes, int n_in,
                              void* d_out, int out_size) {
    const float* ent   = (const float*)d_in[0];
    const float* rel_e = (const float*)d_in[1];
    const int*   sub   = (const int*)d_in[2];
    const int*   rel   = (const int*)d_in[3];
    float* out = (float*)d_out;

    cudaFuncSetAttribute(transe_mma_kernel,
                         cudaFuncAttributeMaxDynamicSharedMemorySize, SMEM_TOT);

    prep_obj<<<BATCH, 128>>>(ent, rel_e, sub, rel);
    transe_mma_kernel<<<N_TILES, THREADS, SMEM_TOT>>>(ent, out);
}